// round 13
// baseline (speedup 1.0000x reference)
#include <cuda_runtime.h>
#include <cuda_fp16.h>
#include <cstdint>

#define NV   32768
#define KC   8192
#define DIMV 64
#define ND   (NV * DIMV)

#define CCHUNK  128                 // codes per chunk
#define NCHUNKS (KC / CCHUNK)       // 64
#define MTILE   128                 // z rows per block
#define NBLK    (NV / MTILE)        // 256
#define ASTRIDE 144                 // bytes per row (64 fp16 = 128B + 16B pad)
#define FIXCAP  2048
#define EPS     0.02f

// SMEM layout (bytes)
#define SM_AH   0
#define SM_AL   18432
#define SM_B    36864                       // 4 x 18432: buf0h, buf0l, buf1h, buf1l
#define SM_BB(i) (SM_B + (i) * 18432)
#define SM_ESQ  110592                      // 2 x 512
#define SM_RB   111616                      // 2*128 floats best
#define SM_RB2  112640                      // 2*128 floats best2
#define SM_RI   113664                      // 2*128 ints idx
#define SM_WL   114688                      // 8 floats warp loss
#define SMEM_BYTES 114720

__device__ __align__(256) __half g_cbh[KC * DIMV];
__device__ __align__(256) __half g_cbl[KC * DIMV];
__device__ float g_esq[KC];                 // 0.5 * ||e||^2 (fp32 exact)
__device__ float g_block_sums[NBLK];
__device__ int   g_fix_count;
__device__ int   g_fix_list[FIXCAP];
__device__ float g_loss_corr;

__device__ __forceinline__ void cp16(void* dst_s, const void* src_g) {
    uint32_t d = (uint32_t)__cvta_generic_to_shared(dst_s);
    asm volatile("cp.async.cg.shared.global [%0], [%1], 16;" :: "r"(d), "l"(src_g));
}
#define CP_COMMIT() asm volatile("cp.async.commit_group;" ::: "memory")
#define CP_WAIT(n)  asm volatile("cp.async.wait_group %0;" :: "n"(n) : "memory")

__device__ __forceinline__ void mma16816(float* c, const uint32_t* a,
                                         uint32_t b0, uint32_t b1) {
    asm volatile(
        "mma.sync.aligned.m16n8k16.row.col.f32.f16.f16.f32 "
        "{%0,%1,%2,%3}, {%4,%5,%6,%7}, {%8,%9}, {%0,%1,%2,%3};"
        : "+f"(c[0]), "+f"(c[1]), "+f"(c[2]), "+f"(c[3])
        : "r"(a[0]), "r"(a[1]), "r"(a[2]), "r"(a[3]), "r"(b0), "r"(b1));
}

// ---------------- Kernel 1: codebook fp16 split + half-norms + resets ----------------
__global__ void vq_prep(const float* __restrict__ cb) {
    int k = blockIdx.x * blockDim.x + threadIdx.x;
    if (k == 0) { g_fix_count = 0; g_loss_corr = 0.f; }
    if (k < KC) {
        float s = 0.f;
        #pragma unroll
        for (int d = 0; d < DIMV; d++) {
            float v = cb[(size_t)k * DIMV + d];
            s += v * v;
            __half h = __float2half_rn(v);
            __half l = __float2half_rn(v - __half2float(h));
            g_cbh[(size_t)k * DIMV + d] = h;
            g_cbl[(size_t)k * DIMV + d] = l;
        }
        g_esq[k] = 0.5f * s;
    }
}

// ---------------- Kernel 2: HMMA distance GEMM + argmin + gather ----------------
__device__ __forceinline__ void cp_chunk(char* smem, int chunk, int buf, int tid) {
    const __half* sh = g_cbh + (size_t)chunk * CCHUNK * DIMV;
    const __half* sl = g_cbl + (size_t)chunk * CCHUNK * DIMV;
    char* dh = smem + SM_BB(2 * buf);
    char* dl = smem + SM_BB(2 * buf + 1);
    #pragma unroll
    for (int n = 0; n < 4; n++) {
        int q = tid + 256 * n;          // 0..1023 16B-quads
        int code = q >> 3, dd = q & 7;
        cp16(dh + code * ASTRIDE + dd * 16, sh + code * DIMV + dd * 8);
        cp16(dl + code * ASTRIDE + dd * 16, sl + code * DIMV + dd * 8);
    }
    if (tid < 32)                       // esq chunk: 128 floats
        cp16(smem + SM_ESQ + (buf ? 512 : 0) + tid * 16, g_esq + chunk * CCHUNK + tid * 4);
}

__global__ __launch_bounds__(256, 1) void vq_main(
    const float* __restrict__ z, const float* __restrict__ cb,
    float* __restrict__ out, int out_size)
{
    extern __shared__ char smem[];
    const int tid = threadIdx.x, lane = tid & 31, wid = tid >> 5;
    const int g = lane >> 2, t = lane & 3;
    const int mwarp = wid >> 1, nwarp = wid & 1;
    const int row0 = blockIdx.x * MTILE;

    // A tile: z fp32 -> fp16 hi/lo, 144B-stride smem
    #pragma unroll
    for (int n = 0; n < 16; n++) {
        int i = tid + 256 * n;          // 0..4095 float2 slots
        int r = i >> 5, d2 = i & 31;
        float2 v = reinterpret_cast<const float2*>(z + (size_t)(row0 + r) * DIMV)[d2];
        __half h0 = __float2half_rn(v.x), h1 = __float2half_rn(v.y);
        __half l0 = __float2half_rn(v.x - __half2float(h0));
        __half l1 = __float2half_rn(v.y - __half2float(h1));
        *reinterpret_cast<__half2*>(smem + SM_AH + r * ASTRIDE + d2 * 4) = __halves2half2(h0, h1);
        *reinterpret_cast<__half2*>(smem + SM_AL + r * ASTRIDE + d2 * 4) = __halves2half2(l0, l1);
    }

    cp_chunk(smem, 0, 0, tid);
    CP_COMMIT();
    __syncthreads();                    // A tile visible to all warps

    float best[4], best2[4];
    int   bidx[4];
    #pragma unroll
    for (int s = 0; s < 4; s++) { best[s] = 3.4e38f; best2[s] = 3.4e38f; bidx[s] = 0; }

    const char* Ah = smem + SM_AH;
    const char* Al = smem + SM_AL;
    const int abase = (mwarp * 32 + g) * ASTRIDE + t * 4;
    const int bbase = (nwarp * 64 + g) * ASTRIDE + t * 4;

    for (int c = 0; c < NCHUNKS; c++) {
        const int b = c & 1;
        if (c + 1 < NCHUNKS) { cp_chunk(smem, c + 1, (c + 1) & 1, tid); CP_COMMIT(); CP_WAIT(1); }
        else                 { CP_WAIT(0); }
        __syncthreads();

        const char* Bh = smem + SM_BB(2 * b);
        const char* Bl = smem + SM_BB(2 * b + 1);
        const float* esq_s = reinterpret_cast<const float*>(smem + SM_ESQ + (b ? 512 : 0));

        float acc[2][8][4];
        #pragma unroll
        for (int mm = 0; mm < 2; mm++)
            #pragma unroll
            for (int nt = 0; nt < 8; nt++)
                #pragma unroll
                for (int q = 0; q < 4; q++) acc[mm][nt][q] = 0.f;

        #pragma unroll
        for (int ks = 0; ks < 4; ks++) {
            uint32_t ahf[2][4], alf[2][4];
            #pragma unroll
            for (int mm = 0; mm < 2; mm++) {
                int ao = abase + mm * 16 * ASTRIDE + ks * 32;
                ahf[mm][0] = *reinterpret_cast<const uint32_t*>(Ah + ao);
                ahf[mm][1] = *reinterpret_cast<const uint32_t*>(Ah + ao + 8 * ASTRIDE);
                ahf[mm][2] = *reinterpret_cast<const uint32_t*>(Ah + ao + 16);
                ahf[mm][3] = *reinterpret_cast<const uint32_t*>(Ah + ao + 8 * ASTRIDE + 16);
                alf[mm][0] = *reinterpret_cast<const uint32_t*>(Al + ao);
                alf[mm][1] = *reinterpret_cast<const uint32_t*>(Al + ao + 8 * ASTRIDE);
                alf[mm][2] = *reinterpret_cast<const uint32_t*>(Al + ao + 16);
                alf[mm][3] = *reinterpret_cast<const uint32_t*>(Al + ao + 8 * ASTRIDE + 16);
            }
            #pragma unroll
            for (int nt = 0; nt < 8; nt++) {
                int bo = bbase + nt * 8 * ASTRIDE + ks * 32;
                uint32_t bh0 = *reinterpret_cast<const uint32_t*>(Bh + bo);
                uint32_t bh1 = *reinterpret_cast<const uint32_t*>(Bh + bo + 16);
                uint32_t bl0 = *reinterpret_cast<const uint32_t*>(Bl + bo);
                uint32_t bl1 = *reinterpret_cast<const uint32_t*>(Bl + bo + 16);
                #pragma unroll
                for (int mm = 0; mm < 2; mm++) {
                    mma16816(acc[mm][nt], ahf[mm], bh0, bh1);   // hh
                    mma16816(acc[mm][nt], ahf[mm], bl0, bl1);   // hl
                    mma16816(acc[mm][nt], alf[mm], bh0, bh1);   // lh
                }
            }
        }

        // Scores + running (best, best2) per row-slot; ascending col order
        #pragma unroll
        for (int nt = 0; nt < 8; nt++) {
            int nloc = nwarp * 64 + nt * 8 + 2 * t;
            float es0 = esq_s[nloc], es1 = esq_s[nloc + 1];
            int n0 = c * CCHUNK + nloc;
            #pragma unroll
            for (int mm = 0; mm < 2; mm++) {
                int s0 = mm * 2, s1 = mm * 2 + 1;
                float v00 = es0 - acc[mm][nt][0];   // row g,   col n0
                float v01 = es1 - acc[mm][nt][1];   // row g,   col n0+1
                float v10 = es0 - acc[mm][nt][2];   // row g+8, col n0
                float v11 = es1 - acc[mm][nt][3];   // row g+8, col n0+1
                if (v00 < best[s0]) { best2[s0] = best[s0]; best[s0] = v00; bidx[s0] = n0; }
                else if (v00 < best2[s0]) best2[s0] = v00;
                if (v01 < best[s0]) { best2[s0] = best[s0]; best[s0] = v01; bidx[s0] = n0 + 1; }
                else if (v01 < best2[s0]) best2[s0] = v01;
                if (v10 < best[s1]) { best2[s1] = best[s1]; best[s1] = v10; bidx[s1] = n0; }
                else if (v10 < best2[s1]) best2[s1] = v10;
                if (v11 < best[s1]) { best2[s1] = best[s1]; best[s1] = v11; bidx[s1] = n0 + 1; }
                else if (v11 < best2[s1]) best2[s1] = v11;
            }
        }
        __syncthreads();                // all warps done with buf b before reissue
    }

    // Reduce over t (lanes xor 1,2 share rows)
    #pragma unroll
    for (int s = 0; s < 4; s++) {
        float b1 = best[s], b2 = best2[s];
        int   i1 = bidx[s];
        #pragma unroll
        for (int off = 1; off <= 2; off <<= 1) {
            float ob  = __shfl_xor_sync(0xffffffffu, b1, off);
            float ob2 = __shfl_xor_sync(0xffffffffu, b2, off);
            int   oi  = __shfl_xor_sync(0xffffffffu, i1, off);
            if (ob < b1 || (ob == b1 && oi < i1)) { b2 = fminf(b1, ob2); b1 = ob; i1 = oi; }
            else                                  { b2 = fminf(ob, b2); }
        }
        best[s] = b1; best2[s] = b2; bidx[s] = i1;
    }
    if (t == 0) {
        float* rb  = reinterpret_cast<float*>(smem + SM_RB);
        float* rb2 = reinterpret_cast<float*>(smem + SM_RB2);
        int*   ri  = reinterpret_cast<int*>(smem + SM_RI);
        #pragma unroll
        for (int s = 0; s < 4; s++) {
            int row = mwarp * 32 + (s >> 1) * 16 + g + (s & 1) * 8;
            rb [nwarp * 128 + row] = best[s];
            rb2[nwarp * 128 + row] = best2[s];
            ri [nwarp * 128 + row] = bidx[s];
        }
    }
    __syncthreads();

    float lsum = 0.f;
    if (tid < MTILE) {
        const float* rb  = reinterpret_cast<const float*>(smem + SM_RB);
        const float* rb2 = reinterpret_cast<const float*>(smem + SM_RB2);
        const int*   ri  = reinterpret_cast<const int*>(smem + SM_RI);
        float b0 = rb[tid],       b20 = rb2[tid];       int i0 = ri[tid];
        float b1 = rb[128 + tid], b21 = rb2[128 + tid]; int i1 = ri[128 + tid];
        float bb, bb2; int bi;
        if (b1 < b0 || (b1 == b0 && i1 < i0)) { bb = b1; bi = i1; bb2 = fminf(b0, b21); }
        else                                  { bb = b0; bi = i0; bb2 = fminf(b1, b20); }

        const int grow = row0 + tid;
        if (bb2 - bb < EPS) {               // ambiguous under tensor error: exact rescan later
            int pos = atomicAdd(&g_fix_count, 1);
            if (pos < FIXCAP) g_fix_list[pos] = grow;
        }
        const float4* crow = reinterpret_cast<const float4*>(cb + (size_t)bi * DIMV);
        const float4* zrow = reinterpret_cast<const float4*>(z + (size_t)grow * DIMV);
        float4* qrow = reinterpret_cast<float4*>(out + (size_t)grow * DIMV);
        #pragma unroll
        for (int j = 0; j < 16; j++) {
            float4 e = crow[j], zz = zrow[j];
            qrow[j] = e;                    // straight-through: quantized == codebook[idx]
            float dx = zz.x - e.x, dy = zz.y - e.y;
            float dz = zz.z - e.z, dw = zz.w - e.w;
            lsum += dx * dx + dy * dy + dz * dz + dw * dw;
        }
        if (out_size >= ND + 2 + NV) out[ND + 2 + grow] = (float)bi;
    }

    #pragma unroll
    for (int off = 16; off >= 1; off >>= 1)
        lsum += __shfl_xor_sync(0xffffffffu, lsum, off);
    float* wl = reinterpret_cast<float*>(smem + SM_WL);
    if (lane == 0) wl[wid] = lsum;
    __syncthreads();
    if (tid == 0) {
        float bsum = 0.f;
        #pragma unroll
        for (int w = 0; w < 8; w++) bsum += wl[w];
        g_block_sums[blockIdx.x] = bsum;
    }
}

// ---------------- Kernel 3: exact fp32 rescan of ambiguous rows ----------------
__global__ void vq_fixup(const float* __restrict__ z, const float* __restrict__ cb,
                         float* __restrict__ out, int out_size) {
    __shared__ float zrow[DIMV];
    __shared__ float sb[256];
    __shared__ int   si[256];
    __shared__ int   s_new;
    if (out_size < ND + 2 + NV) return;
    const int tid = threadIdx.x;
    int nfix = g_fix_count; if (nfix > FIXCAP) nfix = FIXCAP;

    for (int f = blockIdx.x; f < nfix; f += gridDim.x) {
        const int row = g_fix_list[f];
        if (tid < DIMV) zrow[tid] = z[(size_t)row * DIMV + tid];
        __syncthreads();

        float best = 3.4e38f; int bi = 0;
        for (int k = tid; k < KC; k += 256) {   // per-thread ascending => strict < keeps first-min
            const float* e = cb + (size_t)k * DIMV;
            float dot = 0.f;
            #pragma unroll
            for (int d = 0; d < DIMV; d++) dot = fmaf(zrow[d], e[d], dot);
            float s = g_esq[k] - dot;
            if (s < best) { best = s; bi = k; }
        }
        sb[tid] = best; si[tid] = bi;
        __syncthreads();
        for (int st = 128; st >= 1; st >>= 1) {
            if (tid < st) {
                float ob = sb[tid + st]; int oi = si[tid + st];
                if (ob < sb[tid] || (ob == sb[tid] && oi < si[tid])) { sb[tid] = ob; si[tid] = oi; }
            }
            __syncthreads();
        }
        if (tid == 0) {
            int newi = si[0];
            int oldi = (int)out[ND + 2 + row];
            s_new = (newi != oldi) ? newi : -1;
            if (newi != oldi) {
                float lold = 0.f, lnew = 0.f;
                for (int d = 0; d < DIMV; d++) {
                    float zz = zrow[d];
                    float eo = cb[(size_t)oldi * DIMV + d];
                    float en = cb[(size_t)newi * DIMV + d];
                    lold += (zz - eo) * (zz - eo);
                    lnew += (zz - en) * (zz - en);
                }
                atomicAdd(&g_loss_corr, lnew - lold);
                out[ND + 2 + row] = (float)newi;
            }
        }
        __syncthreads();
        if (s_new >= 0 && tid < DIMV)
            out[(size_t)row * DIMV + tid] = cb[(size_t)s_new * DIMV + tid];
        __syncthreads();
    }
}

// ---------------- Kernel 4: deterministic final losses ----------------
__global__ void vq_finalize(float* __restrict__ out, int out_size) {
    __shared__ float ws[8];
    int tid = threadIdx.x;
    float s = g_block_sums[tid];        // NBLK == 256 == blockDim
    #pragma unroll
    for (int off = 16; off >= 1; off >>= 1)
        s += __shfl_xor_sync(0xffffffffu, s, off);
    if ((tid & 31) == 0) ws[tid >> 5] = s;
    __syncthreads();
    if (tid == 0) {
        float b = 0.f;
        #pragma unroll
        for (int w = 0; w < 8; w++) b += ws[w];
        float m = (b + g_loss_corr) / (float)ND;
        if (out_size >= ND + 2) {
            out[ND]     = m;   // vq_loss
            out[ND + 1] = m;   // commitment_loss
        }
    }
}

extern "C" void kernel_launch(void* const* d_in, const int* in_sizes, int n_in,
                              void* d_out, int out_size) {
    const float* a = (const float*)d_in[0];
    const float* b = (const float*)d_in[1];
    const float* z;
    const float* cb;
    if (in_sizes[0] == NV * DIMV) { z = a; cb = b; }
    else                          { z = b; cb = a; }
    float* out = (float*)d_out;

    cudaFuncSetAttribute(vq_main, cudaFuncAttributeMaxDynamicSharedMemorySize, SMEM_BYTES);

    vq_prep<<<KC / 128, 128>>>(cb);
    vq_main<<<NBLK, 256, SMEM_BYTES>>>(z, cb, out, out_size);
    vq_fixup<<<64, 256>>>(z, cb, out, out_size);
    vq_finalize<<<1, 256>>>(out, out_size);
}

// round 14
// speedup vs baseline: 2.0647x; 2.0647x over previous
#include <cuda_runtime.h>
#include <cuda_fp16.h>
#include <cstdint>

#define NV   32768
#define KC   8192
#define DIMV 64
#define ND   (NV * DIMV)

// ---- main kernel geometry ----
#define ROWS    32                   // z rows per block
#define NBLK    (NV / ROWS)          // 1024
#define CCH     512                  // codes per chunk
#define NCH     (KC / CCH)           // 16
#define ESTR    144                  // bytes per fp16 row (128B data + 16B pad)
#define EBUF    (CCH * ESTR)         // 73728
#define EPS     0.25f
#define FIXCAP  16384

// main smem layout (bytes)
#define SM_Z    0                    // 32 * 144 = 4608
#define SM_E    4608                 // 2 * EBUF = 147456
#define SM_ESQ  152064               // 2 * 2048
#define SM_RED  156160               // rb(1024) + rb2(1024) + ri(1024)
#define SMEM_MAIN 159232

// ---- fixup kernel geometry ----
#define FROWS   16                   // flagged rows per group
#define FCCH    256                  // fp32 codes per chunk
#define FNCH    (KC / FCCH)          // 32
#define FSTR    272                  // bytes per fp32 row (256B + 16B pad)
#define FEBUF   (FCCH * FSTR)        // 69632
#define FSM_Z   0                    // 16 * 272 = 4352
#define FSM_E   4352                 // 2 * FEBUF = 139264
#define FSM_RED 143616               // rb(512) + ri(512)
#define SMEM_FIX 144640

__device__ __align__(256) __half g_cbh[KC * DIMV];
__device__ float g_esq[KC];          // 0.5 * ||e||^2 (exact fp32)
__device__ float g_block_sums[NBLK];
__device__ int   g_fix_count;
__device__ int   g_fix_list[FIXCAP];
__device__ float g_loss_corr;

struct alignas(8) H22 { __half2 a, b; };

__device__ __forceinline__ void cp16(void* dst_s, const void* src_g) {
    uint32_t d = (uint32_t)__cvta_generic_to_shared(dst_s);
    asm volatile("cp.async.cg.shared.global [%0], [%1], 16;" :: "r"(d), "l"(src_g));
}
#define CP_COMMIT() asm volatile("cp.async.commit_group;" ::: "memory")
#define CP_WAIT1()  asm volatile("cp.async.wait_group 1;" ::: "memory")
#define CP_WAIT0()  asm volatile("cp.async.wait_group 0;" ::: "memory")

__device__ __forceinline__ void ffma2(unsigned long long &d,
                                      unsigned long long a,
                                      unsigned long long b) {
    asm("fma.rn.f32x2 %0, %1, %2, %0;" : "+l"(d) : "l"(a), "l"(b));
}

// ---------------- Kernel 1: codebook fp16 + exact half-norms + resets ----------------
__global__ void vq_prep(const float* __restrict__ cb) {
    int k = blockIdx.x * blockDim.x + threadIdx.x;
    if (k == 0) { g_fix_count = 0; g_loss_corr = 0.f; }
    if (k < KC) {
        float s = 0.f;
        #pragma unroll
        for (int d = 0; d < DIMV; d++) {
            float v = cb[(size_t)k * DIMV + d];
            s += v * v;
            g_cbh[(size_t)k * DIMV + d] = __float2half_rn(v);
        }
        g_esq[k] = 0.5f * s;
    }
}

// ---------------- Kernel 2: HFMA2 distance + argmin/margin + gather ----------------
__device__ __forceinline__ void cp_chunk(char* smem, int chunk, int buf, int tid) {
    const __half* s = g_cbh + (size_t)chunk * CCH * DIMV;
    char* d = smem + SM_E + buf * EBUF;
    #pragma unroll
    for (int n = 0; n < 16; n++) {
        int q = tid + 256 * n;           // 0..4095 16B-quads
        int code = q >> 3, dd = q & 7;
        cp16(d + code * ESTR + dd * 16, s + code * DIMV + dd * 8);
    }
    if (tid < 128)                       // esq chunk: 512 floats
        cp16(smem + SM_ESQ + buf * 2048 + tid * 16, g_esq + chunk * CCH + tid * 4);
}

__global__ __launch_bounds__(256, 1) void vq_main(
    const float* __restrict__ z, const float* __restrict__ cb,
    float* __restrict__ out, int out_size)
{
    extern __shared__ char smem[];
    const int tid  = threadIdx.x, lane = tid & 31, wid = tid >> 5;
    const int row_t = lane & 3;          // 4 row-threads per warp (8 rows each)
    const int csub  = lane >> 2;         // 8 col-subthreads per warp
    const int ct    = wid * 8 + csub;    // 0..63 col-threads (8 codes each per chunk)
    const int row0  = blockIdx.x * ROWS;

    // z tile: fp32 -> fp16, 144B-stride smem
    #pragma unroll
    for (int n = 0; n < 4; n++) {
        int i = tid + 256 * n;           // 0..1023 float2 slots
        int r = i >> 5, d2 = i & 31;
        float2 v = reinterpret_cast<const float2*>(z + (size_t)(row0 + r) * DIMV)[d2];
        *reinterpret_cast<__half2*>(smem + SM_Z + r * ESTR + d2 * 4) =
            __halves2half2(__float2half_rn(v.x), __float2half_rn(v.y));
    }

    cp_chunk(smem, 0, 0, tid);
    CP_COMMIT();

    float best[8], best2[8];
    int   bidx[8];
    #pragma unroll
    for (int k = 0; k < 8; k++) { best[k] = 3.4e38f; best2[k] = 3.4e38f; bidx[k] = 0; }

    const char* Zs = smem + SM_Z;

    for (int c = 0; c < NCH; c++) {
        const int b = c & 1;
        if (c + 1 < NCH) { cp_chunk(smem, c + 1, (c + 1) & 1, tid); CP_COMMIT(); CP_WAIT1(); }
        else             { CP_WAIT0(); }
        __syncthreads();

        const char* Eb = smem + SM_E + b * EBUF;
        const float* esq_s = reinterpret_cast<const float*>(smem + SM_ESQ + b * 2048);

        __half2 acc[8][8];
        #pragma unroll
        for (int k = 0; k < 8; k++)
            #pragma unroll
            for (int j = 0; j < 8; j++) acc[k][j] = __halves2half2(__ushort_as_half(0), __ushort_as_half(0));

        #pragma unroll 4
        for (int d4 = 0; d4 < 16; d4++) {          // 4 dims per iter
            H22 zf[8], ef[8];
            #pragma unroll
            for (int k = 0; k < 8; k++)
                zf[k] = *reinterpret_cast<const H22*>(Zs + (row_t + 4 * k) * ESTR + d4 * 8);
            #pragma unroll
            for (int j = 0; j < 8; j++)
                ef[j] = *reinterpret_cast<const H22*>(Eb + (ct + 64 * j) * ESTR + d4 * 8);
            #pragma unroll
            for (int k = 0; k < 8; k++)
                #pragma unroll
                for (int j = 0; j < 8; j++) {
                    acc[k][j] = __hfma2(zf[k].a, ef[j].a, acc[k][j]);
                    acc[k][j] = __hfma2(zf[k].b, ef[j].b, acc[k][j]);
                }
        }

        // fold + running (best, best2); within-thread ascending code index
        #pragma unroll
        for (int j = 0; j < 8; j++) {
            int code = c * CCH + ct + 64 * j;
            float es = esq_s[ct + 64 * j];
            #pragma unroll
            for (int k = 0; k < 8; k++) {
                float2 f = __half22float2(acc[k][j]);
                float s = es - f.x - f.y;
                if (s < best[k]) { best2[k] = best[k]; best[k] = s; bidx[k] = code; }
                else if (s < best2[k]) best2[k] = s;
            }
        }
        __syncthreads();                 // all warps done with buf b before reissue
    }

    // warp reduce over csub (xor 4,8,16 keep row_t)
    #pragma unroll
    for (int k = 0; k < 8; k++) {
        float b1 = best[k], b2 = best2[k];
        int   i1 = bidx[k];
        #pragma unroll
        for (int off = 4; off <= 16; off <<= 1) {
            float ob  = __shfl_xor_sync(0xffffffffu, b1, off);
            float ob2 = __shfl_xor_sync(0xffffffffu, b2, off);
            int   oi  = __shfl_xor_sync(0xffffffffu, i1, off);
            if (ob < b1 || (ob == b1 && oi < i1)) { b2 = fminf(b1, ob2); b1 = ob; i1 = oi; }
            else                                  { b2 = fminf(ob, b2); }
        }
        best[k] = b1; best2[k] = b2; bidx[k] = i1;
    }
    float* rb  = reinterpret_cast<float*>(smem + SM_RED);
    float* rb2 = rb + 256;
    int*   ri  = reinterpret_cast<int*>(rb + 512);
    if (csub == 0) {
        #pragma unroll
        for (int k = 0; k < 8; k++) {
            int r = row_t + 4 * k;
            rb [wid * 32 + r] = best[k];
            rb2[wid * 32 + r] = best2[k];
            ri [wid * 32 + r] = bidx[k];
        }
    }
    __syncthreads();

    if (tid < ROWS) {
        const int r = tid;
        float b1 = 3.4e38f, b2 = 3.4e38f; int i1 = 0;
        #pragma unroll
        for (int w = 0; w < 8; w++) {
            float ob = rb[w * 32 + r], ob2 = rb2[w * 32 + r];
            int   oi = ri[w * 32 + r];
            if (ob < b1 || (ob == b1 && oi < i1)) { b2 = fminf(b1, ob2); b1 = ob; i1 = oi; }
            else                                  { b2 = fminf(ob, b2); }
        }
        const int grow = row0 + r;
        if (b2 - b1 < EPS) {             // ambiguous under fp16 error: exact rescan later
            int pos = atomicAdd(&g_fix_count, 1);
            if (pos < FIXCAP) g_fix_list[pos] = grow;
        }
        float lsum = 0.f;
        const float4* crow = reinterpret_cast<const float4*>(cb + (size_t)i1 * DIMV);
        const float4* zrow = reinterpret_cast<const float4*>(z + (size_t)grow * DIMV);
        float4* qrow = reinterpret_cast<float4*>(out + (size_t)grow * DIMV);
        #pragma unroll
        for (int j = 0; j < 16; j++) {
            float4 e = crow[j], zz = zrow[j];
            qrow[j] = e;                 // straight-through: quantized == codebook[idx]
            float dx = zz.x - e.x, dy = zz.y - e.y;
            float dz = zz.z - e.z, dw = zz.w - e.w;
            lsum += dx * dx + dy * dy + dz * dz + dw * dw;
        }
        if (out_size >= ND + 2 + NV) out[ND + 2 + grow] = (float)i1;

        #pragma unroll
        for (int off = 16; off >= 1; off >>= 1)
            lsum += __shfl_xor_sync(0xffffffffu, lsum, off);
        if (r == 0) g_block_sums[blockIdx.x] = lsum;
    }
}

// ---------------- Kernel 3: exact fp32 rescan, 16 flagged rows per group ----------------
__global__ __launch_bounds__(256, 1) void vq_fixup(
    const float* __restrict__ z, const float* __restrict__ cb,
    float* __restrict__ out, int out_size)
{
    extern __shared__ char fsm[];
    if (out_size < ND + 2 + NV) return;
    const int tid = threadIdx.x, lane = tid & 31, wid = tid >> 5;
    const int row_t = lane & 3, csub = lane >> 2;
    const int ct = wid * 8 + csub;       // 0..63 col-threads, 4 codes each per chunk
    int nfix = g_fix_count; if (nfix > FIXCAP) nfix = FIXCAP;

    float* z_s = reinterpret_cast<float*>(fsm + FSM_Z);
    float* rbf = reinterpret_cast<float*>(fsm + FSM_RED);
    int*   rif = reinterpret_cast<int*>(rbf + 128);

    for (int g = blockIdx.x; g * FROWS < nfix; g += gridDim.x) {
        const int base = g * FROWS;
        const int cnt  = min(FROWS, nfix - base);
        __syncthreads();                 // z_s / e reuse across groups

        // gather flagged z rows (fp32) into smem
        for (int i = tid; i < FROWS * 16; i += 256) {
            int r = i >> 4, qd = i & 15;
            int zr = g_fix_list[base + min(r, cnt - 1)];
            float4 v = reinterpret_cast<const float4*>(z + (size_t)zr * DIMV)[qd];
            *reinterpret_cast<float4*>(z_s + r * 68 + qd * 4) = v;
        }
        // preload chunk 0 (fp32 codebook)
        #pragma unroll
        for (int n = 0; n < 16; n++) {
            int q = tid + 256 * n;       // 0..4095 quads
            int code = q >> 4, dd = q & 15;
            cp16(fsm + FSM_E + code * FSTR + dd * 16, cb + (size_t)code * DIMV + dd * 4);
        }
        CP_COMMIT();

        float best[4];
        int   bidx[4];
        #pragma unroll
        for (int k = 0; k < 4; k++) { best[k] = 3.4e38f; bidx[k] = 0; }

        for (int c = 0; c < FNCH; c++) {
            const int b = c & 1;
            if (c + 1 < FNCH) {
                const float* src = cb + (size_t)(c + 1) * FCCH * DIMV;
                char* d = fsm + FSM_E + ((c + 1) & 1) * FEBUF;
                #pragma unroll
                for (int n = 0; n < 16; n++) {
                    int q = tid + 256 * n;
                    int code = q >> 4, dd = q & 15;
                    cp16(d + code * FSTR + dd * 16, src + (size_t)code * DIMV + dd * 4);
                }
                CP_COMMIT(); CP_WAIT1();
            } else CP_WAIT0();
            __syncthreads();

            const char* Eb = fsm + FSM_E + b * FEBUF;
            unsigned long long acc[4][4];
            #pragma unroll
            for (int k = 0; k < 4; k++)
                #pragma unroll
                for (int j = 0; j < 4; j++) acc[k][j] = 0ull;

            #pragma unroll 8
            for (int d2 = 0; d2 < 32; d2++) {
                unsigned long long zf[4], ef[4];
                #pragma unroll
                for (int k = 0; k < 4; k++)
                    zf[k] = *reinterpret_cast<const unsigned long long*>(
                        z_s + (row_t + 4 * k) * 68 + d2 * 2);
                #pragma unroll
                for (int j = 0; j < 4; j++)
                    ef[j] = *reinterpret_cast<const unsigned long long*>(
                        Eb + (ct + 64 * j) * FSTR + d2 * 8);
                #pragma unroll
                for (int k = 0; k < 4; k++)
                    #pragma unroll
                    for (int j = 0; j < 4; j++) ffma2(acc[k][j], zf[k], ef[j]);
            }

            #pragma unroll
            for (int j = 0; j < 4; j++) {
                int code = c * FCCH + ct + 64 * j;
                float es = __ldg(&g_esq[code]);
                #pragma unroll
                for (int k = 0; k < 4; k++) {
                    float lo = __uint_as_float((unsigned)(acc[k][j] & 0xffffffffull));
                    float hi = __uint_as_float((unsigned)(acc[k][j] >> 32));
                    float s = es - (lo + hi);
                    if (s < best[k]) { best[k] = s; bidx[k] = code; }
                }
            }
            __syncthreads();
        }

        // reduce over csub then warps
        #pragma unroll
        for (int k = 0; k < 4; k++) {
            float b1 = best[k]; int i1 = bidx[k];
            #pragma unroll
            for (int off = 4; off <= 16; off <<= 1) {
                float ob = __shfl_xor_sync(0xffffffffu, b1, off);
                int   oi = __shfl_xor_sync(0xffffffffu, i1, off);
                if (ob < b1 || (ob == b1 && oi < i1)) { b1 = ob; i1 = oi; }
            }
            best[k] = b1; bidx[k] = i1;
        }
        if (csub == 0) {
            #pragma unroll
            for (int k = 0; k < 4; k++) {
                int r = row_t + 4 * k;
                rbf[wid * 16 + r] = best[k];
                rif[wid * 16 + r] = bidx[k];
            }
        }
        __syncthreads();

        if (tid < cnt) {
            float b1 = 3.4e38f; int i1 = 0;
            #pragma unroll
            for (int w = 0; w < 8; w++) {
                float ob = rbf[w * 16 + tid]; int oi = rif[w * 16 + tid];
                if (ob < b1 || (ob == b1 && oi < i1)) { b1 = ob; i1 = oi; }
            }
            const int row  = g_fix_list[base + tid];
            const int oldi = (int)out[ND + 2 + row];
            if (i1 != oldi) {
                float lold = 0.f, lnew = 0.f;
                #pragma unroll
                for (int d = 0; d < DIMV; d++) {
                    float zz = z[(size_t)row * DIMV + d];
                    float eo = cb[(size_t)oldi * DIMV + d];
                    float en = cb[(size_t)i1 * DIMV + d];
                    lold += (zz - eo) * (zz - eo);
                    lnew += (zz - en) * (zz - en);
                }
                atomicAdd(&g_loss_corr, lnew - lold);
                out[ND + 2 + row] = (float)i1;
                #pragma unroll
                for (int j = 0; j < 16; j++)
                    reinterpret_cast<float4*>(out + (size_t)row * DIMV)[j] =
                        reinterpret_cast<const float4*>(cb + (size_t)i1 * DIMV)[j];
            }
        }
    }
}

// ---------------- Kernel 4: deterministic final losses ----------------
__global__ void vq_finalize(float* __restrict__ out, int out_size) {
    __shared__ float ws[8];
    int tid = threadIdx.x;
    float s = 0.f;
    #pragma unroll
    for (int i = 0; i < NBLK / 256; i++) s += g_block_sums[tid + 256 * i];
    #pragma unroll
    for (int off = 16; off >= 1; off >>= 1)
        s += __shfl_xor_sync(0xffffffffu, s, off);
    if ((tid & 31) == 0) ws[tid >> 5] = s;
    __syncthreads();
    if (tid == 0) {
        float b = 0.f;
        #pragma unroll
        for (int w = 0; w < 8; w++) b += ws[w];
        float m = (b + g_loss_corr) / (float)ND;
        if (out_size >= ND + 2) {
            out[ND]     = m;   // vq_loss
            out[ND + 1] = m;   // commitment_loss
        }
    }
}

extern "C" void kernel_launch(void* const* d_in, const int* in_sizes, int n_in,
                              void* d_out, int out_size) {
    const float* a = (const float*)d_in[0];
    const float* b = (const float*)d_in[1];
    const float* z;
    const float* cb;
    if (in_sizes[0] == NV * DIMV) { z = a; cb = b; }
    else                          { z = b; cb = a; }
    float* out = (float*)d_out;

    cudaFuncSetAttribute(vq_main,  cudaFuncAttributeMaxDynamicSharedMemorySize, SMEM_MAIN);
    cudaFuncSetAttribute(vq_fixup, cudaFuncAttributeMaxDynamicSharedMemorySize, SMEM_FIX);

    vq_prep<<<KC / 128, 128>>>(cb);
    vq_main<<<NBLK, 256, SMEM_MAIN>>>(z, cb, out, out_size);
    vq_fixup<<<512, 256, SMEM_FIX>>>(z, cb, out, out_size);
    vq_finalize<<<1, 256>>>(out, out_size);
}